// round 16
// baseline (speedup 1.0000x reference)
#include <cuda_runtime.h>
#include <cuda_bf16.h>
#include <cstdint>

#define NTOK 4096
#define BATCH 4
#define CIN 256
#define DI 128
#define DV 256
#define OUTC 256

typedef unsigned long long u64;
typedef uint32_t u32;
typedef unsigned short u16s;

__device__ __forceinline__ void mmabf(float4& d, u32 a0, u32 a1, u32 a2, u32 a3,
                                      u32 b0, u32 b1) {
    asm volatile(
        "mma.sync.aligned.m16n8k16.row.col.f32.bf16.bf16.f32 "
        "{%0,%1,%2,%3}, {%4,%5,%6,%7}, {%8,%9}, {%0,%1,%2,%3};"
        : "+f"(d.x), "+f"(d.y), "+f"(d.z), "+f"(d.w)
        : "r"(a0), "r"(a1), "r"(a2), "r"(a3), "r"(b0), "r"(b1));
}
__device__ __forceinline__ void mmaf8(float4& d, u32 a0, u32 a1, u32 a2, u32 a3,
                                      u32 b0, u32 b1) {
    asm volatile(
        "mma.sync.aligned.m16n8k32.row.col.f32.e4m3.e4m3.f32 "
        "{%0,%1,%2,%3}, {%4,%5,%6,%7}, {%8,%9}, {%0,%1,%2,%3};"
        : "+f"(d.x), "+f"(d.y), "+f"(d.z), "+f"(d.w)
        : "r"(a0), "r"(a1), "r"(a2), "r"(a3), "r"(b0), "r"(b1));
}
__device__ __forceinline__ void ldmx4(u32& r0, u32& r1, u32& r2, u32& r3, u32 a) {
    asm volatile("ldmatrix.sync.aligned.m8n8.x4.shared.b16 {%0,%1,%2,%3}, [%4];"
                 : "=r"(r0), "=r"(r1), "=r"(r2), "=r"(r3) : "r"(a));
}
__device__ __forceinline__ void ldmx4t(u32& r0, u32& r1, u32& r2, u32& r3, u32 a) {
    asm volatile("ldmatrix.sync.aligned.m8n8.x4.trans.shared.b16 {%0,%1,%2,%3}, [%4];"
                 : "=r"(r0), "=r"(r1), "=r"(r2), "=r"(r3) : "r"(a));
}
__device__ __forceinline__ u32 pkbf(float lo, float hi) {
    u32 r; asm("cvt.rn.bf16x2.f32 %0, %1, %2;" : "=r"(r) : "f"(hi), "f"(lo)); return r;
}
__device__ __forceinline__ u16s pk8(float lo, float hi) {
    u16s r; asm("cvt.rn.satfinite.e4m3x2.f32 %0, %1, %2;" : "=h"(r) : "f"(hi), "f"(lo));
    return r;
}
__device__ __forceinline__ u32 pk8x4(float a, float b, float c, float d) {
    u16s lo = pk8(a, b), hi = pk8(c, d);
    return (u32)lo | ((u32)hi << 16);
}
__device__ __forceinline__ float ex2f(float x) {
    float r; asm("ex2.approx.f32 %0, %1;" : "=f"(r) : "f"(x)); return r;
}
__device__ __forceinline__ u32 smaddr(const void* p) {
    return (u32)__cvta_generic_to_shared(p);
}
__device__ __forceinline__ void cp16(u32 dst, const void* src) {
    asm volatile("cp.async.cg.shared.global [%0], [%1], 16;" :: "r"(dst), "l"(src));
}
#define CP_COMMIT() asm volatile("cp.async.commit_group;")
#define CP_WAIT1()  asm volatile("cp.async.wait_group 1;")
#define CP_WAIT0()  asm volatile("cp.async.wait_group 0;")

// ---------------- scratch ----------------
__device__ __nv_bfloat16 g_x1h[BATCH * CIN * NTOK];
__device__ __nv_bfloat16 g_x2h[BATCH * CIN * NTOK];
__device__ __nv_bfloat16 g_Wh[3 * 128 * 256];
__device__ __nv_bfloat16 g_Wph[256 * 256];
__device__ __nv_bfloat16 g_Qh[BATCH * NTOK * DI];    // pre-scaled by 128^-0.5*log2(e)
__device__ __nv_bfloat16 g_Kh[BATCH * NTOK * DI];
__device__ __nv_bfloat16 g_Vh[BATCH * NTOK * DV];    // [0:128)=v2, [128:256)=v1
__device__ uint8_t g_Vt8[BATCH * DV * NTOK];         // fp8 V transposed [vc][tok]
__device__ __nv_bfloat16 g_corrh[BATCH * NTOK * DV];
__device__ float g_csum[BATCH * DV];
__device__ float g_base[BATCH * OUTC];

__global__ void zero_csum_kernel() { g_csum[threadIdx.x] = 0.0f; }

__global__ void cvt_x_kernel(const float* __restrict__ x1, const float* __restrict__ x2) {
    const float* src = blockIdx.y ? x2 : x1;
    __nv_bfloat16* dst = blockIdx.y ? g_x2h : g_x1h;
    int idx = (blockIdx.x * 256 + threadIdx.x) * 4;
    float4 v = *(const float4*)&src[idx];
    *(uint2*)&dst[idx] = make_uint2(pkbf(v.x, v.y), pkbf(v.z, v.w));
}

__global__ void cvt_w_kernel(const float* __restrict__ Wq, const float* __restrict__ Wk,
                             const float* __restrict__ Wv, const float* __restrict__ Wp) {
    int y = blockIdx.y;
    const float* src = (y == 0) ? Wq : (y == 1) ? Wk : (y == 2) ? Wv : Wp;
    __nv_bfloat16* dst = (y < 3) ? (g_Wh + y * 32768) : g_Wph;
    int n = (y < 3) ? 32768 : 65536;
    int idx = (blockIdx.x * 256 + threadIdx.x) * 4;
    if (idx < n) {
        float4 v = *(const float4*)&src[idx];
        *(uint2*)&dst[idx] = make_uint2(pkbf(v.x, v.y), pkbf(v.z, v.w));
    }
}

__global__ void base_kernel(const float* __restrict__ Wp, const float* __restrict__ bp) {
    __shared__ float cs[256];
    int b = blockIdx.x, o = threadIdx.x;
    cs[o] = g_csum[b * DV + o];
    __syncthreads();
    float s = bp[o];
    const float* w = Wp + (size_t)o * 256;
#pragma unroll 8
    for (int c = 0; c < 256; ++c) s += w[c] * cs[c];
    g_base[b * OUTC + o] = s;
}

// V transpose+quantize: g_Vh [b][n][256] bf16 -> g_Vt8 [b][vc][4096] fp8.
__global__ __launch_bounds__(256)
void vt8_kernel() {
    __shared__ uint16_t sm[64 * 260];
    const int b = blockIdx.y, n0 = blockIdx.x * 64, tid = threadIdx.x;
    const __nv_bfloat16* src = g_Vh + ((size_t)b * NTOK + n0) * DV;
#pragma unroll
    for (int it = 0; it < 32; ++it) {
        int idx = tid + it * 256;
        int r = idx >> 7, c = idx & 127;
        *(u32*)&sm[r * 260 + c * 2] = *(const u32*)&src[(size_t)r * DV + c * 2];
    }
    __syncthreads();
    uint8_t* dst = g_Vt8 + ((size_t)b * DV + tid) * NTOK + n0;
#pragma unroll
    for (int i = 0; i < 16; ++i) {
        float f0 = __bfloat162float(*(__nv_bfloat16*)&sm[(4 * i + 0) * 260 + tid]);
        float f1 = __bfloat162float(*(__nv_bfloat16*)&sm[(4 * i + 1) * 260 + tid]);
        float f2 = __bfloat162float(*(__nv_bfloat16*)&sm[(4 * i + 2) * 260 + tid]);
        float f3 = __bfloat162float(*(__nv_bfloat16*)&sm[(4 * i + 3) * 260 + tid]);
        ((u32*)dst)[i] = pk8x4(f0, f1, f2, f3);
    }
}

// ============================================================================
// QKV projection (round-14 body, unchanged)
// ============================================================================
#define XS_S 72
#define WS_S 264
#define QK_OFFW 18432
#define QK_OFFC 52224
#define SMEM_QKV (52224 * 2 + 512)

__global__ __launch_bounds__(256, 2)
void qkv_tc_kernel(const float* __restrict__ bq, const float* __restrict__ sq,
                   const float* __restrict__ tq,
                   const float* __restrict__ bk, const float* __restrict__ sk,
                   const float* __restrict__ tk,
                   const float* __restrict__ bv, const float* __restrict__ sv,
                   const float* __restrict__ tv) {
    extern __shared__ uint16_t qsm[];
    float* colacc = (float*)(qsm + QK_OFFC);
    const int z = blockIdx.z, b = blockIdx.y, nbase = blockIdx.x * 64;
    const int tid = threadIdx.x, lane = tid & 31, wid = tid >> 5;
    const int wn = wid & 3, wo = wid >> 2;
    const int gq = lane >> 2, qd = lane & 3;
    const __nv_bfloat16* xh = (z == 0 || z == 3) ? g_x1h : g_x2h;
    const __nv_bfloat16* wg = g_Wh + (z < 2 ? z : 2) * 32768;
    const float* bias = (z == 0) ? bq : (z == 1) ? bk : bv;
    const float* sc = (z == 0) ? sq : (z == 1) ? sk : sv;
    const float* tr = (z == 0) ? tq : (z == 1) ? tk : tv;
    const float prescale = (z == 0) ? 0.12751743f : 1.0f;
    const u32 smbase = smaddr(qsm);

    if (tid < 128) colacc[tid] = 0.0f;

    const __nv_bfloat16* xg = xh + (size_t)b * CIN * NTOK + nbase;
    const int seg8 = (tid & 7) * 8;
    const int r32 = tid >> 3;
#pragma unroll
    for (int c = 0; c < 4; ++c) {
#pragma unroll
        for (int it = 0; it < 2; ++it) {
            int r = 64 * c + r32 + 32 * it;
            cp16(smbase + (r * XS_S + seg8) * 2, xg + (size_t)r * NTOK + seg8);
        }
#pragma unroll
        for (int it = 0; it < 4; ++it) {
            int r = r32 + 32 * it;
            cp16(smbase + (QK_OFFW + r * WS_S + 64 * c + seg8) * 2,
                 wg + (size_t)r * 256 + 64 * c + seg8);
        }
        CP_COMMIT();
    }

    const u32 aX = smbase + ((((lane & 7) + ((lane >> 4) & 1) * 8)) * XS_S +
                             16 * wn + ((lane >> 3) & 1) * 8) * 2;
    const u32 aW = smbase + (QK_OFFW + (64 * wo + (lane & 7) + ((lane >> 4) & 1) * 8) * WS_S +
                             ((lane >> 3) & 1) * 8) * 2;

    float4 acc[8];
#pragma unroll
    for (int t = 0; t < 8; ++t) acc[t] = make_float4(0.f, 0.f, 0.f, 0.f);

#pragma unroll
    for (int c = 0; c < 4; ++c) {
        if (c == 0)      asm volatile("cp.async.wait_group 3;");
        else if (c == 1) asm volatile("cp.async.wait_group 2;");
        else if (c == 2) asm volatile("cp.async.wait_group 1;");
        else             asm volatile("cp.async.wait_group 0;");
        __syncthreads();
#pragma unroll
        for (int kkl = 0; kkl < 4; ++kkl) {
            int kk = 4 * c + kkl;
            u32 a0, a1, a2, a3;
            ldmx4t(a0, a1, a2, a3, aX + kk * 16 * XS_S * 2);
#pragma unroll
            for (int j = 0; j < 4; ++j) {
                u32 b0, b1, b2, b3;
                ldmx4(b0, b1, b2, b3, aW + (j * 16 * WS_S + kk * 16) * 2);
                mmabf(acc[2 * j], a0, a1, a2, a3, b0, b1);
                mmabf(acc[2 * j + 1], a0, a1, a2, a3, b2, b3);
            }
        }
    }

    const int n0 = 16 * wn + gq;
    const size_t rg = (size_t)b * NTOK + nbase + n0;
#pragma unroll
    for (int t = 0; t < 8; ++t) {
        int o = 64 * wo + 8 * t + 2 * qd;
        float2 bb = *(const float2*)&bias[o];
        float2 ss = *(const float2*)&sc[o];
        float2 tt = *(const float2*)&tr[o];
        float v00 = fmaxf((acc[t].x + bb.x) * ss.x + tt.x, 0.f) * prescale;
        float v01 = fmaxf((acc[t].y + bb.y) * ss.y + tt.y, 0.f) * prescale;
        float v10 = fmaxf((acc[t].z + bb.x) * ss.x + tt.x, 0.f) * prescale;
        float v11 = fmaxf((acc[t].w + bb.y) * ss.y + tt.y, 0.f) * prescale;
        if (z == 0) {
            *(u32*)&g_Qh[rg * DI + o] = pkbf(v00, v01);
            *(u32*)&g_Qh[(rg + 8) * DI + o] = pkbf(v10, v11);
        } else if (z == 1) {
            *(u32*)&g_Kh[rg * DI + o] = pkbf(v00, v01);
            *(u32*)&g_Kh[(rg + 8) * DI + o] = pkbf(v10, v11);
        } else {
            int oc = o + (z == 3 ? 128 : 0);
            *(u32*)&g_Vh[rg * DV + oc] = pkbf(v00, v01);
            *(u32*)&g_Vh[(rg + 8) * DV + oc] = pkbf(v10, v11);
            atomicAdd(&colacc[o], v00 + v10);
            atomicAdd(&colacc[o + 1], v01 + v11);
        }
    }
    if (z >= 2) {
        __syncthreads();
        if (tid < 128) {
            int ofs = (z == 3) ? 128 : 0;
            atomicAdd(&g_csum[b * DV + ofs + tid], colacc[tid]);
        }
    }
}

// ============================================================================
// Flash attention: QK bf16 m16n8k16, PV fp8 m16n8k32 (V^T fp8, P fp8).
// BR=128, BC=128, NO-MAX softmax. Byte-offset smem map:
//   Q [0,34816) K [34816,69632) V8 2x36864 [69632,143360) P8 [143360,161792)
//   red [161792,162816)
// ============================================================================
#define OQ 0
#define OK 34816
#define OV 69632
#define VSZ 36864
#define OP 143360
#define ORED 161792
#define SMEM_ATTN 162816
#define QKS 272
#define VS8 144
#define P8S 144
#define SHIFT 8.0f

__global__ __launch_bounds__(256, 1)
void attn_kernel() {
    extern __shared__ char smb[];
    float* red = (float*)(smb + ORED);
    const int b = blockIdx.y;
    const int nbase = blockIdx.x * 128;
    const int tid = threadIdx.x, lane = tid & 31, wid = tid >> 5;
    const int wr = wid >> 1, wc = wid & 1;
    const int wp = wid >> 2, wq = wid & 3;
    const int gq = lane >> 2, qd = lane & 3;
    const u32 smbase = smaddr(smb);

    const int rQ = tid >> 4, cQb = (tid & 15) * 16;   // bf16 rows: 16 cp16/row
    const char* Qg = (const char*)(g_Qh + ((size_t)b * NTOK + nbase) * DI);
    const char* Kg0 = (const char*)(g_Kh + (size_t)b * NTOK * DI);
    const uint8_t* Vt = g_Vt8 + (size_t)b * DV * NTOK;

    // prologue: group0 = {Q, K(0)}, group1 = {V8(0)}
#pragma unroll
    for (int it = 0; it < 8; ++it) {
        int r = rQ + 16 * it;
        cp16(smbase + OQ + r * QKS + cQb, Qg + (size_t)r * 256 + cQb);
        cp16(smbase + OK + r * QKS + cQb, Kg0 + (size_t)r * 256 + cQb);
    }
    CP_COMMIT();
#pragma unroll
    for (int c = 0; c < 8; ++c)
        cp16(smbase + OV + tid * VS8 + c * 16, Vt + (size_t)tid * NTOK + c * 16);
    CP_COMMIT();

    const u32 aQ0 = smbase + OQ + (32 * wr + (lane & 15)) * QKS + (lane >> 4) * 16;
    const u32 aQ1 = aQ0 + 16 * QKS;
    const u32 aKb = smbase + OK +
        (64 * wc + (lane & 7) + ((lane >> 4) & 1) * 8) * QKS + ((lane >> 3) & 1) * 16;
    const u32 aP8 = smbase + OP + (64 * wp + (lane & 15)) * P8S + (lane >> 4) * 16;
    const u32 aV8off = (64 * wq + (lane & 15)) * VS8 + (lane >> 4) * 16;

    float Lp[4] = {0.f, 0.f, 0.f, 0.f};
    float4 acc[4][8];
#pragma unroll
    for (int rf = 0; rf < 4; ++rf)
#pragma unroll
        for (int t = 0; t < 8; ++t) acc[rf][t] = make_float4(0.f, 0.f, 0.f, 0.f);

    for (int tl = 0; tl < 32; ++tl) {
        const bool more = (tl + 1) < 32;
        CP_WAIT1();           // K(tl) (and Q) resident
        __syncthreads();      // (A)

        // ---- S = Q K^T (bf16), exp2(S-SHIFT) -> P8, two 32-col halves ----
#pragma unroll
        for (int ch = 0; ch < 2; ++ch) {
            float4 S[2][4];
#pragma unroll
            for (int f = 0; f < 2; ++f)
#pragma unroll
                for (int t = 0; t < 4; ++t) S[f][t] = make_float4(0.f, 0.f, 0.f, 0.f);
            const u32 aK = aKb + ch * (32 * QKS);
            const u32 aK2 = aK + 16 * QKS;
#pragma unroll
            for (int kk = 0; kk < 8; ++kk) {
                u32 q00, q01, q02, q03, q10, q11, q12, q13;
                ldmx4(q00, q01, q02, q03, aQ0 + kk * 32);
                ldmx4(q10, q11, q12, q13, aQ1 + kk * 32);
                u32 b00, b01, b10, b11, b20, b21, b30, b31;
                ldmx4(b00, b01, b10, b11, aK + kk * 32);
                ldmx4(b20, b21, b30, b31, aK2 + kk * 32);
                mmabf(S[0][0], q00, q01, q02, q03, b00, b01);
                mmabf(S[0][1], q00, q01, q02, q03, b10, b11);
                mmabf(S[0][2], q00, q01, q02, q03, b20, b21);
                mmabf(S[0][3], q00, q01, q02, q03, b30, b31);
                mmabf(S[1][0], q10, q11, q12, q13, b00, b01);
                mmabf(S[1][1], q10, q11, q12, q13, b10, b11);
                mmabf(S[1][2], q10, q11, q12, q13, b20, b21);
                mmabf(S[1][3], q10, q11, q12, q13, b30, b31);
            }
#pragma unroll
            for (int f = 0; f < 2; ++f) {
                int r0 = 32 * wr + 16 * f + gq;
                float s0 = 0.0f, s1 = 0.0f;
#pragma unroll
                for (int t = 0; t < 4; ++t) {
                    S[f][t].x = ex2f(S[f][t].x - SHIFT);
                    S[f][t].y = ex2f(S[f][t].y - SHIFT);
                    S[f][t].z = ex2f(S[f][t].z - SHIFT);
                    S[f][t].w = ex2f(S[f][t].w - SHIFT);
                    s0 += S[f][t].x + S[f][t].y;
                    s1 += S[f][t].z + S[f][t].w;
                    int col = 64 * wc + 32 * ch + 8 * t + 2 * qd;
                    *(u16s*)(smb + OP + r0 * P8S + col) = pk8(S[f][t].x, S[f][t].y);
                    *(u16s*)(smb + OP + (r0 + 8) * P8S + col) = pk8(S[f][t].z, S[f][t].w);
                }
                Lp[2 * f] += s0;
                Lp[2 * f + 1] += s1;
            }
        }
        CP_WAIT0();           // V8(tl) resident
        __syncthreads();      // (B) K consumed + P8 visible + V8 visible

        // prefetch K(tl+1) (overlaps PV)
        if (more) {
            const char* Kg = Kg0 + (size_t)(tl + 1) * 128 * 256;
#pragma unroll
            for (int it = 0; it < 8; ++it) {
                int r = rQ + 16 * it;
                cp16(smbase + OK + r * QKS + cQb, Kg + (size_t)r * 256 + cQb);
            }
            CP_COMMIT();
        }

        // ---- O += P V (fp8 m16n8k32, k=128 over 4 steps) ----
        const u32 vb = smbase + OV + (tl & 1) * VSZ;
#pragma unroll
        for (int kk = 0; kk < 4; ++kk) {
            u32 pa[4][4];
#pragma unroll
            for (int rf = 0; rf < 4; ++rf)
                ldmx4(pa[rf][0], pa[rf][1], pa[rf][2], pa[rf][3],
                      aP8 + rf * (16 * P8S) + kk * 32);
#pragma unroll
            for (int g = 0; g < 4; ++g) {
                u32 r0, r1, r2, r3;
                ldmx4(r0, r1, r2, r3, vb + aV8off + g * (16 * VS8) + kk * 32);
#pragma unroll
                for (int rf = 0; rf < 4; ++rf) {
                    mmaf8(acc[rf][2 * g], pa[rf][0], pa[rf][1], pa[rf][2], pa[rf][3], r0, r2);
                    mmaf8(acc[rf][2 * g + 1], pa[rf][0], pa[rf][1], pa[rf][2], pa[rf][3], r1, r3);
                }
            }
        }
        __syncthreads();      // (D) V8/P8 consumers done

        // prefetch V8(tl+1) (overlaps next S)
        if (more) {
            const uint8_t* Vg = Vt + (size_t)(tl + 1) * 128;
            u32 vd = smbase + OV + ((tl + 1) & 1) * VSZ;
#pragma unroll
            for (int c = 0; c < 8; ++c)
                cp16(vd + tid * VS8 + c * 16, Vg + (size_t)tid * NTOK + c * 16);
            CP_COMMIT();
        }
    }

    // ---- epilogue: reduce L, write corr = acc / L (bf16) ----
#pragma unroll
    for (int f = 0; f < 2; ++f) {
        float s0 = Lp[2 * f], s1 = Lp[2 * f + 1];
        s0 += __shfl_xor_sync(0xffffffffu, s0, 1);
        s0 += __shfl_xor_sync(0xffffffffu, s0, 2);
        s1 += __shfl_xor_sync(0xffffffffu, s1, 1);
        s1 += __shfl_xor_sync(0xffffffffu, s1, 2);
        if (qd == 0) {
            int r0 = 32 * wr + 16 * f + gq;
            red[wc * 128 + r0] = s0;
            red[wc * 128 + r0 + 8] = s1;
        }
    }
    __syncthreads();
    __nv_bfloat16* og = g_corrh + ((size_t)b * NTOK + nbase) * DV;
#pragma unroll
    for (int rf = 0; rf < 4; ++rf) {
        int ra = 64 * wp + 16 * rf + gq;
        float ia = 1.0f / (red[ra] + red[128 + ra]);
        float ib = 1.0f / (red[ra + 8] + red[128 + ra + 8]);
#pragma unroll
        for (int t = 0; t < 8; ++t) {
            int col = 64 * wq + 8 * t + 2 * qd;
            *(u32*)&og[(size_t)ra * DV + col] = pkbf(acc[rf][t].x * ia, acc[rf][t].y * ia);
            *(u32*)&og[(size_t)(ra + 8) * DV + col] = pkbf(acc[rf][t].z * ib, acc[rf][t].w * ib);
        }
    }
}

// ============================================================================
// Output projection (round-14 body, unchanged)
// ============================================================================
#define PF_OFFW 16896
#define SMEM_PF ((16896 + 33792) * 2)

__global__ __launch_bounds__(256, 2)
void projf_tc_kernel(const float* __restrict__ sp, const float* __restrict__ tp,
                     float* __restrict__ out) {
    extern __shared__ uint16_t psm[];
    const int b = blockIdx.z, obase = blockIdx.y * 128, nbase = blockIdx.x * 64;
    const int tid = threadIdx.x, lane = tid & 31, wid = tid >> 5;
    const int gq = lane >> 2, qd = lane & 3;
    const u32 smbase = smaddr(psm);

    {
        const __nv_bfloat16* cg = g_corrh + ((size_t)b * NTOK + nbase) * DV;
        int seg = (tid & 31) * 8;
#pragma unroll
        for (int it = 0; it < 8; ++it) {
            int r = (tid >> 5) + 8 * it;
            cp16(smbase + (r * WS_S + seg) * 2, cg + (size_t)r * DV + seg);
        }
        const __nv_bfloat16* wg = g_Wph + (size_t)obase * 256;
#pragma unroll
        for (int it = 0; it < 16; ++it) {
            int r = (tid >> 5) + 8 * it;
            cp16(smbase + (PF_OFFW + r * WS_S + seg) * 2, wg + (size_t)r * 256 + seg);
        }
    }
    CP_COMMIT(); CP_WAIT0();
    __syncthreads();

    const u32 aA = smbase + (PF_OFFW + (16 * wid + (lane & 15)) * WS_S + (lane >> 4) * 8) * 2;
    const u32 aB = smbase + (((lane & 7) + ((lane >> 4) & 1) * 8) * WS_S +
                             ((lane >> 3) & 1) * 8) * 2;

    float4 acc[8];
#pragma unroll
    for (int t = 0; t < 8; ++t) acc[t] = make_float4(0.f, 0.f, 0.f, 0.f);

#pragma unroll
    for (int kk = 0; kk < 16; ++kk) {
        u32 a0, a1, a2, a3;
        ldmx4(a0, a1, a2, a3, aA + kk * 16 * 2);
#pragma unroll
        for (int j = 0; j < 4; ++j) {
            u32 b0, b1, b2, b3;
            ldmx4(b0, b1, b2, b3, aB + (j * 16 * WS_S + kk * 16) * 2);
            mmabf(acc[2 * j], a0, a1, a2, a3, b0, b1);
            mmabf(acc[2 * j + 1], a0, a1, a2, a3, b2, b3);
        }
    }

    const int o0 = obase + 16 * wid + gq;
    float bs0 = g_base[b * OUTC + o0], bs1 = g_base[b * OUTC + o0 + 8];
    float sp0 = sp[o0], sp1 = sp[o0 + 8], tp0 = tp[o0], tp1 = tp[o0 + 8];
    float* og0 = out + ((size_t)b * OUTC + o0) * NTOK + nbase;
    float* og1 = og0 + (size_t)8 * NTOK;
#pragma unroll
    for (int t = 0; t < 8; ++t) {
        int n = 8 * t + 2 * qd;
        float2 r0, r1;
        r0.x = fmaxf((bs0 - acc[t].x) * sp0 + tp0, 0.f);
        r0.y = fmaxf((bs0 - acc[t].y) * sp0 + tp0, 0.f);
        r1.x = fmaxf((bs1 - acc[t].z) * sp1 + tp1, 0.f);
        r1.y = fmaxf((bs1 - acc[t].w) * sp1 + tp1, 0.f);
        *(float2*)&og0[n] = r0;
        *(float2*)&og1[n] = r1;
    }
}

extern "C" void kernel_launch(void* const* d_in, const int* in_sizes, int n_in,
                              void* d_out, int out_size) {
    const float* x1 = (const float*)d_in[0];
    const float* x2 = (const float*)d_in[1];
    const float* Wq = (const float*)d_in[2];
    const float* bq = (const float*)d_in[3];
    const float* sq = (const float*)d_in[4];
    const float* tq = (const float*)d_in[5];
    const float* Wk = (const float*)d_in[6];
    const float* bk = (const float*)d_in[7];
    const float* sk = (const float*)d_in[8];
    const float* tk = (const float*)d_in[9];
    const float* Wv = (const float*)d_in[10];
    const float* bv = (const float*)d_in[11];
    const float* sv = (const float*)d_in[12];
    const float* tv = (const float*)d_in[13];
    const float* Wp = (const float*)d_in[14];
    const float* bp = (const float*)d_in[15];
    const float* sp = (const float*)d_in[16];
    const float* tp = (const float*)d_in[17];
    float* out = (float*)d_out;

    cudaFuncSetAttribute(qkv_tc_kernel, cudaFuncAttributeMaxDynamicSharedMemorySize, SMEM_QKV);
    cudaFuncSetAttribute(attn_kernel, cudaFuncAttributeMaxDynamicSharedMemorySize, SMEM_ATTN);
    cudaFuncSetAttribute(projf_tc_kernel, cudaFuncAttributeMaxDynamicSharedMemorySize, SMEM_PF);

    cvt_x_kernel<<<dim3(4096, 2), 256>>>(x1, x2);
    cvt_w_kernel<<<dim3(64, 4), 256>>>(Wq, Wk, Wv, Wp);
    zero_csum_kernel<<<1, BATCH * DV>>>();
    qkv_tc_kernel<<<dim3(NTOK / 64, BATCH, 4), 256, SMEM_QKV>>>(
        bq, sq, tq, bk, sk, tk, bv, sv, tv);
    vt8_kernel<<<dim3(NTOK / 64, BATCH), 256>>>();
    base_kernel<<<BATCH, 256>>>(Wp, bp);
    attn_kernel<<<dim3(NTOK / 128, BATCH), 256, SMEM_ATTN>>>();
    projf_tc_kernel<<<dim3(NTOK / 64, OUTC / 128, BATCH), 256, SMEM_PF>>>(sp, tp, out);
}

// round 17
// speedup vs baseline: 1.1498x; 1.1498x over previous
#include <cuda_runtime.h>
#include <cuda_bf16.h>
#include <cstdint>

#define NTOK 4096
#define BATCH 4
#define CIN 256
#define DI 128
#define DV 256
#define OUTC 256

typedef unsigned long long u64;
typedef uint32_t u32;

__device__ __forceinline__ void mmabf(float4& d, u32 a0, u32 a1, u32 a2, u32 a3,
                                      u32 b0, u32 b1) {
    asm volatile(
        "mma.sync.aligned.m16n8k16.row.col.f32.bf16.bf16.f32 "
        "{%0,%1,%2,%3}, {%4,%5,%6,%7}, {%8,%9}, {%0,%1,%2,%3};"
        : "+f"(d.x), "+f"(d.y), "+f"(d.z), "+f"(d.w)
        : "r"(a0), "r"(a1), "r"(a2), "r"(a3), "r"(b0), "r"(b1));
}
__device__ __forceinline__ void ldmx4(u32& r0, u32& r1, u32& r2, u32& r3, u32 a) {
    asm volatile("ldmatrix.sync.aligned.m8n8.x4.shared.b16 {%0,%1,%2,%3}, [%4];"
                 : "=r"(r0), "=r"(r1), "=r"(r2), "=r"(r3) : "r"(a));
}
__device__ __forceinline__ void ldmx4t(u32& r0, u32& r1, u32& r2, u32& r3, u32 a) {
    asm volatile("ldmatrix.sync.aligned.m8n8.x4.trans.shared.b16 {%0,%1,%2,%3}, [%4];"
                 : "=r"(r0), "=r"(r1), "=r"(r2), "=r"(r3) : "r"(a));
}
__device__ __forceinline__ u32 pkbf(float lo, float hi) {
    u32 r; asm("cvt.rn.bf16x2.f32 %0, %1, %2;" : "=r"(r) : "f"(hi), "f"(lo)); return r;
}
__device__ __forceinline__ float ex2f(float x) {
    float r; asm("ex2.approx.f32 %0, %1;" : "=f"(r) : "f"(x)); return r;
}
__device__ __forceinline__ u32 smaddr(const void* p) {
    return (u32)__cvta_generic_to_shared(p);
}
__device__ __forceinline__ void cp16(u32 dst, const void* src) {
    asm volatile("cp.async.cg.shared.global [%0], [%1], 16;" :: "r"(dst), "l"(src));
}
#define CP_COMMIT() asm volatile("cp.async.commit_group;")
#define CP_WAIT1()  asm volatile("cp.async.wait_group 1;")
#define CP_WAIT0()  asm volatile("cp.async.wait_group 0;")

// ---------------- scratch ----------------
__device__ __nv_bfloat16 g_x1h[BATCH * CIN * NTOK];
__device__ __nv_bfloat16 g_x2h[BATCH * CIN * NTOK];
__device__ __nv_bfloat16 g_Wh[3 * 128 * 256];
__device__ __nv_bfloat16 g_Wph[256 * 256];
__device__ __nv_bfloat16 g_Qh[BATCH * NTOK * DI];    // pre-scaled by 128^-0.5 * log2(e)
__device__ __nv_bfloat16 g_Kh[BATCH * NTOK * DI];
__device__ __nv_bfloat16 g_Vh[BATCH * NTOK * DV];    // [0:128)=v2, [128:256)=v1
__device__ __nv_bfloat16 g_corrh[BATCH * NTOK * DV]; // P·V/L (bf16)
__device__ float g_csum[BATCH * DV];
__device__ float g_base[BATCH * OUTC];

// ---------------- tiny kernels ----------------
__global__ void cvt_x_kernel(const float* __restrict__ x1, const float* __restrict__ x2) {
    const float* src = blockIdx.y ? x2 : x1;
    __nv_bfloat16* dst = blockIdx.y ? g_x2h : g_x1h;
    int idx = (blockIdx.x * 256 + threadIdx.x) * 4;
    float4 v = *(const float4*)&src[idx];
    *(uint2*)&dst[idx] = make_uint2(pkbf(v.x, v.y), pkbf(v.z, v.w));
}

// y<4: weight conversion; y==4 (x<4): zero csum
__global__ void cvt_w_kernel(const float* __restrict__ Wq, const float* __restrict__ Wk,
                             const float* __restrict__ Wv, const float* __restrict__ Wp) {
    int y = blockIdx.y;
    if (y == 4) {
        if (blockIdx.x < 4) g_csum[blockIdx.x * 256 + threadIdx.x] = 0.0f;
        return;
    }
    const float* src = (y == 0) ? Wq : (y == 1) ? Wk : (y == 2) ? Wv : Wp;
    __nv_bfloat16* dst = (y < 3) ? (g_Wh + y * 32768) : g_Wph;
    int n = (y < 3) ? 32768 : 65536;
    int idx = (blockIdx.x * 256 + threadIdx.x) * 4;
    if (idx < n) {
        float4 v = *(const float4*)&src[idx];
        *(uint2*)&dst[idx] = make_uint2(pkbf(v.x, v.y), pkbf(v.z, v.w));
    }
}

__global__ void base_kernel(const float* __restrict__ Wp, const float* __restrict__ bp) {
    __shared__ float cs[256];
    int b = blockIdx.x, o = threadIdx.x;
    cs[o] = g_csum[b * DV + o];
    __syncthreads();
    float s = bp[o];
    const float* w = Wp + (size_t)o * 256;
#pragma unroll 8
    for (int c = 0; c < 256; ++c) s += w[c] * cs[c];
    g_base[b * OUTC + o] = s;
}

// ============================================================================
// QKV projection (round-14 body, unchanged)
// ============================================================================
#define XS_S 72
#define WS_S 264
#define QK_OFFW 18432
#define QK_OFFC 52224
#define SMEM_QKV (52224 * 2 + 512)

__global__ __launch_bounds__(256, 2)
void qkv_tc_kernel(const float* __restrict__ bq, const float* __restrict__ sq,
                   const float* __restrict__ tq,
                   const float* __restrict__ bk, const float* __restrict__ sk,
                   const float* __restrict__ tk,
                   const float* __restrict__ bv, const float* __restrict__ sv,
                   const float* __restrict__ tv) {
    extern __shared__ uint16_t qsm[];
    float* colacc = (float*)(qsm + QK_OFFC);
    const int z = blockIdx.z, b = blockIdx.y, nbase = blockIdx.x * 64;
    const int tid = threadIdx.x, lane = tid & 31, wid = tid >> 5;
    const int wn = wid & 3, wo = wid >> 2;
    const int gq = lane >> 2, qd = lane & 3;
    const __nv_bfloat16* xh = (z == 0 || z == 3) ? g_x1h : g_x2h;
    const __nv_bfloat16* wg = g_Wh + (z < 2 ? z : 2) * 32768;
    const float* bias = (z == 0) ? bq : (z == 1) ? bk : bv;
    const float* sc = (z == 0) ? sq : (z == 1) ? sk : sv;
    const float* tr = (z == 0) ? tq : (z == 1) ? tk : tv;
    const float prescale = (z == 0) ? 0.12751743f : 1.0f;
    const u32 smbase = smaddr(qsm);

    if (tid < 128) colacc[tid] = 0.0f;

    const __nv_bfloat16* xg = xh + (size_t)b * CIN * NTOK + nbase;
    const int seg8 = (tid & 7) * 8;
    const int r32 = tid >> 3;
#pragma unroll
    for (int c = 0; c < 4; ++c) {
#pragma unroll
        for (int it = 0; it < 2; ++it) {
            int r = 64 * c + r32 + 32 * it;
            cp16(smbase + (r * XS_S + seg8) * 2, xg + (size_t)r * NTOK + seg8);
        }
#pragma unroll
        for (int it = 0; it < 4; ++it) {
            int r = r32 + 32 * it;
            cp16(smbase + (QK_OFFW + r * WS_S + 64 * c + seg8) * 2,
                 wg + (size_t)r * 256 + 64 * c + seg8);
        }
        CP_COMMIT();
    }

    const u32 aX = smbase + ((((lane & 7) + ((lane >> 4) & 1) * 8)) * XS_S +
                             16 * wn + ((lane >> 3) & 1) * 8) * 2;
    const u32 aW = smbase + (QK_OFFW + (64 * wo + (lane & 7) + ((lane >> 4) & 1) * 8) * WS_S +
                             ((lane >> 3) & 1) * 8) * 2;

    float4 acc[8];
#pragma unroll
    for (int t = 0; t < 8; ++t) acc[t] = make_float4(0.f, 0.f, 0.f, 0.f);

#pragma unroll
    for (int c = 0; c < 4; ++c) {
        if (c == 0)      asm volatile("cp.async.wait_group 3;");
        else if (c == 1) asm volatile("cp.async.wait_group 2;");
        else if (c == 2) asm volatile("cp.async.wait_group 1;");
        else             asm volatile("cp.async.wait_group 0;");
        __syncthreads();
#pragma unroll
        for (int kkl = 0; kkl < 4; ++kkl) {
            int kk = 4 * c + kkl;
            u32 a0, a1, a2, a3;
            ldmx4t(a0, a1, a2, a3, aX + kk * 16 * XS_S * 2);
#pragma unroll
            for (int j = 0; j < 4; ++j) {
                u32 b0, b1, b2, b3;
                ldmx4(b0, b1, b2, b3, aW + (j * 16 * WS_S + kk * 16) * 2);
                mmabf(acc[2 * j], a0, a1, a2, a3, b0, b1);
                mmabf(acc[2 * j + 1], a0, a1, a2, a3, b2, b3);
            }
        }
    }

    const int n0 = 16 * wn + gq;
    const size_t rg = (size_t)b * NTOK + nbase + n0;
#pragma unroll
    for (int t = 0; t < 8; ++t) {
        int o = 64 * wo + 8 * t + 2 * qd;
        float2 bb = *(const float2*)&bias[o];
        float2 ss = *(const float2*)&sc[o];
        float2 tt = *(const float2*)&tr[o];
        float v00 = fmaxf((acc[t].x + bb.x) * ss.x + tt.x, 0.f) * prescale;
        float v01 = fmaxf((acc[t].y + bb.y) * ss.y + tt.y, 0.f) * prescale;
        float v10 = fmaxf((acc[t].z + bb.x) * ss.x + tt.x, 0.f) * prescale;
        float v11 = fmaxf((acc[t].w + bb.y) * ss.y + tt.y, 0.f) * prescale;
        if (z == 0) {
            *(u32*)&g_Qh[rg * DI + o] = pkbf(v00, v01);
            *(u32*)&g_Qh[(rg + 8) * DI + o] = pkbf(v10, v11);
        } else if (z == 1) {
            *(u32*)&g_Kh[rg * DI + o] = pkbf(v00, v01);
            *(u32*)&g_Kh[(rg + 8) * DI + o] = pkbf(v10, v11);
        } else {
            int oc = o + (z == 3 ? 128 : 0);
            *(u32*)&g_Vh[rg * DV + oc] = pkbf(v00, v01);
            *(u32*)&g_Vh[(rg + 8) * DV + oc] = pkbf(v10, v11);
            atomicAdd(&colacc[o], v00 + v10);
            atomicAdd(&colacc[o + 1], v01 + v11);
        }
    }
    if (z >= 2) {
        __syncthreads();
        if (tid < 128) {
            int ofs = (z == 3) ? 128 : 0;
            atomicAdd(&g_csum[b * DV + ofs + tid], colacc[tid]);
        }
    }
}

// ============================================================================
// bf16 flash attention, NO-MAX softmax, BR=128, BC=128 (round-14 body)
// ============================================================================
#define QK_S 136
#define V_S  264
#define P_S  136
#define OFF_K 17408
#define OFF_V 34816
#define OFF_P 68608
#define OFF_RED 86016
#define SMEM_ATTN (OFF_RED * 2 + 256 * 4)
#define SHIFT 8.0f

__global__ __launch_bounds__(256, 1)
void attn_kernel() {
    extern __shared__ uint16_t smh[];
    float* red = (float*)(smh + OFF_RED);

    const int b = blockIdx.y;
    const int nbase = blockIdx.x * 128;
    const int tid = threadIdx.x;
    const int wid = tid >> 5, lane = tid & 31;
    const int wr = wid >> 1, wc = wid & 1;
    const int wp = wid >> 2, wq = wid & 3;
    const int gq = lane >> 2, qd = lane & 3;

    const int rQ = tid >> 4, cQ = (tid & 15) * 8;
    const int rV = tid >> 5, cV = (tid & 31) * 8;
    const __nv_bfloat16* Qg = g_Qh + ((size_t)b * NTOK + nbase) * DI;
    const __nv_bfloat16* Kg0 = g_Kh + (size_t)b * NTOK * DI;
    const __nv_bfloat16* Vg0 = g_Vh + (size_t)b * NTOK * DV;
    const u32 smbase = smaddr(smh);

#pragma unroll
    for (int it = 0; it < 8; ++it) {
        int r = rQ + 16 * it;
        cp16(smbase + (r * QK_S + cQ) * 2, Qg + (size_t)r * DI + cQ);
        cp16(smbase + (OFF_K + r * QK_S + cQ) * 2, Kg0 + (size_t)r * DI + cQ);
    }
    CP_COMMIT();
#pragma unroll
    for (int it = 0; it < 16; ++it) {
        int r = rV + 8 * it;
        cp16(smbase + (OFF_V + r * V_S + cV) * 2, Vg0 + (size_t)r * DV + cV);
    }
    CP_COMMIT();

    const u32 aQ0 = smbase + ((32 * wr + (lane & 15)) * QK_S + (lane >> 4) * 8) * 2;
    const u32 aQ1 = aQ0 + 16 * QK_S * 2;
    const u32 aKbase = smbase + OFF_K * 2 +
        ((64 * wc + (lane & 7) + ((lane >> 4) & 1) * 8) * QK_S + ((lane >> 3) & 1) * 8) * 2;
    const u32 aPb = smbase + (OFF_P + (64 * wp + (lane & 15)) * P_S + (lane >> 4) * 8) * 2;
    const u32 aVb = smbase + OFF_V * 2 +
        (((lane & 7) + ((lane >> 3) & 1) * 8) * V_S + 64 * wq + (lane >> 4) * 8) * 2;

    float Lp[4] = {0.f, 0.f, 0.f, 0.f};
    float4 acc[4][8];
#pragma unroll
    for (int rf = 0; rf < 4; ++rf)
#pragma unroll
        for (int t = 0; t < 8; ++t) acc[rf][t] = make_float4(0.f, 0.f, 0.f, 0.f);

    for (int tl = 0; tl < 32; ++tl) {
        const bool more = (tl + 1) < 32;
        CP_WAIT1();
        __syncthreads();      // (A)

#pragma unroll
        for (int ch = 0; ch < 2; ++ch) {
            float4 S[2][4];
#pragma unroll
            for (int f = 0; f < 2; ++f)
#pragma unroll
                for (int t = 0; t < 4; ++t) S[f][t] = make_float4(0.f, 0.f, 0.f, 0.f);
            const u32 aK = aKbase + ch * (32 * QK_S * 2);
            const u32 aK2 = aK + 16 * QK_S * 2;
#pragma unroll
            for (int kk = 0; kk < 8; ++kk) {
                u32 q00, q01, q02, q03, q10, q11, q12, q13;
                ldmx4(q00, q01, q02, q03, aQ0 + kk * 32);
                ldmx4(q10, q11, q12, q13, aQ1 + kk * 32);
                u32 b00, b01, b10, b11, b20, b21, b30, b31;
                ldmx4(b00, b01, b10, b11, aK + kk * 32);
                ldmx4(b20, b21, b30, b31, aK2 + kk * 32);
                mmabf(S[0][0], q00, q01, q02, q03, b00, b01);
                mmabf(S[0][1], q00, q01, q02, q03, b10, b11);
                mmabf(S[0][2], q00, q01, q02, q03, b20, b21);
                mmabf(S[0][3], q00, q01, q02, q03, b30, b31);
                mmabf(S[1][0], q10, q11, q12, q13, b00, b01);
                mmabf(S[1][1], q10, q11, q12, q13, b10, b11);
                mmabf(S[1][2], q10, q11, q12, q13, b20, b21);
                mmabf(S[1][3], q10, q11, q12, q13, b30, b31);
            }
#pragma unroll
            for (int f = 0; f < 2; ++f) {
                int r0 = 32 * wr + 16 * f + gq;
                float s0 = 0.0f, s1 = 0.0f;
#pragma unroll
                for (int t = 0; t < 4; ++t) {
                    S[f][t].x = ex2f(S[f][t].x - SHIFT);
                    S[f][t].y = ex2f(S[f][t].y - SHIFT);
                    S[f][t].z = ex2f(S[f][t].z - SHIFT);
                    S[f][t].w = ex2f(S[f][t].w - SHIFT);
                    s0 += S[f][t].x + S[f][t].y;
                    s1 += S[f][t].z + S[f][t].w;
                    int col = 64 * wc + 32 * ch + 8 * t + 2 * qd;
                    *(u32*)(smh + OFF_P + r0 * P_S + col) = pkbf(S[f][t].x, S[f][t].y);
                    *(u32*)(smh + OFF_P + (r0 + 8) * P_S + col) = pkbf(S[f][t].z, S[f][t].w);
                }
                Lp[2 * f] += s0;
                Lp[2 * f + 1] += s1;
            }
        }
        CP_WAIT0();
        __syncthreads();      // (B) K consumed + P visible + V visible

        if (more) {
            const __nv_bfloat16* Kg = Kg0 + (size_t)(tl + 1) * 128 * DI;
#pragma unroll
            for (int it = 0; it < 8; ++it) {
                int r = rQ + 16 * it;
                cp16(smbase + (OFF_K + r * QK_S + cQ) * 2, Kg + (size_t)r * DI + cQ);
            }
            CP_COMMIT();
        }

#pragma unroll
        for (int kk = 0; kk < 8; ++kk) {
            u32 pa[4][4];
#pragma unroll
            for (int rf = 0; rf < 4; ++rf)
                ldmx4(pa[rf][0], pa[rf][1], pa[rf][2], pa[rf][3],
                      aPb + rf * (16 * P_S * 2) + kk * 32);
            u32 vrow = aVb + kk * (16 * V_S * 2);
#pragma unroll
            for (int p = 0; p < 4; ++p) {
                u32 b0, b1, b2, b3;
                ldmx4t(b0, b1, b2, b3, vrow + p * 32);
#pragma unroll
                for (int rf = 0; rf < 4; ++rf) {
                    mmabf(acc[rf][2 * p], pa[rf][0], pa[rf][1], pa[rf][2], pa[rf][3], b0, b1);
                    mmabf(acc[rf][2 * p + 1], pa[rf][0], pa[rf][1], pa[rf][2], pa[rf][3], b2, b3);
                }
            }
        }
        __syncthreads();      // (D)

        if (more) {
            const __nv_bfloat16* Vg = Vg0 + (size_t)(tl + 1) * 128 * DV;
#pragma unroll
            for (int it = 0; it < 16; ++it) {
                int r = rV + 8 * it;
                cp16(smbase + (OFF_V + r * V_S + cV) * 2, Vg + (size_t)r * DV + cV);
            }
            CP_COMMIT();
        }
    }

#pragma unroll
    for (int f = 0; f < 2; ++f) {
        float s0 = Lp[2 * f], s1 = Lp[2 * f + 1];
        s0 += __shfl_xor_sync(0xffffffffu, s0, 1);
        s0 += __shfl_xor_sync(0xffffffffu, s0, 2);
        s1 += __shfl_xor_sync(0xffffffffu, s1, 1);
        s1 += __shfl_xor_sync(0xffffffffu, s1, 2);
        if (qd == 0) {
            int r0 = 32 * wr + 16 * f + gq;
            red[wc * 128 + r0] = s0;
            red[wc * 128 + r0 + 8] = s1;
        }
    }
    __syncthreads();
    __nv_bfloat16* og = g_corrh + ((size_t)b * NTOK + nbase) * DV;
#pragma unroll
    for (int rf = 0; rf < 4; ++rf) {
        int ra = 64 * wp + 16 * rf + gq;
        float ia = 1.0f / (red[ra] + red[128 + ra]);
        float ib = 1.0f / (red[ra + 8] + red[128 + ra + 8]);
#pragma unroll
        for (int t = 0; t < 8; ++t) {
            int col = 64 * wq + 8 * t + 2 * qd;
            *(u32*)&og[(size_t)ra * DV + col] = pkbf(acc[rf][t].x * ia, acc[rf][t].y * ia);
            *(u32*)&og[(size_t)(ra + 8) * DV + col] = pkbf(acc[rf][t].z * ib, acc[rf][t].w * ib);
        }
    }
}

// ============================================================================
// Output projection, 4-chunk k pipeline (k=64 slices of corr + Wp).
// ============================================================================
#define PF_OFFW 16896
#define SMEM_PF ((16896 + 33792) * 2)

__global__ __launch_bounds__(256, 2)
void projf_tc_kernel(const float* __restrict__ sp, const float* __restrict__ tp,
                     float* __restrict__ out) {
    extern __shared__ uint16_t psm[];
    const int b = blockIdx.z, obase = blockIdx.y * 128, nbase = blockIdx.x * 64;
    const int tid = threadIdx.x, lane = tid & 31, wid = tid >> 5;
    const int gq = lane >> 2, qd = lane & 3;
    const u32 smbase = smaddr(psm);

    const __nv_bfloat16* cg = g_corrh + ((size_t)b * NTOK + nbase) * DV;
    const __nv_bfloat16* wg = g_Wph + (size_t)obase * 256;
    const int seg8 = (tid & 7) * 8;
    const int r32 = tid >> 3;
#pragma unroll
    for (int c = 0; c < 4; ++c) {
        // corr: 64 rows x 64 k-cols
#pragma unroll
        for (int it = 0; it < 2; ++it) {
            int r = r32 + 32 * it;
            cp16(smbase + (r * WS_S + 64 * c + seg8) * 2,
                 cg + (size_t)r * DV + 64 * c + seg8);
        }
        // W: 128 rows x 64 k-cols
#pragma unroll
        for (int it = 0; it < 4; ++it) {
            int r = r32 + 32 * it;
            cp16(smbase + (PF_OFFW + r * WS_S + 64 * c + seg8) * 2,
                 wg + (size_t)r * 256 + 64 * c + seg8);
        }
        CP_COMMIT();
    }

    const u32 aA = smbase + (PF_OFFW + (16 * wid + (lane & 15)) * WS_S + (lane >> 4) * 8) * 2;
    const u32 aB = smbase + (((lane & 7) + ((lane >> 4) & 1) * 8) * WS_S +
                             ((lane >> 3) & 1) * 8) * 2;

    float4 acc[8];
#pragma unroll
    for (int t = 0; t < 8; ++t) acc[t] = make_float4(0.f, 0.f, 0.f, 0.f);

#pragma unroll
    for (int c = 0; c < 4; ++c) {
        if (c == 0)      asm volatile("cp.async.wait_group 3;");
        else if (c == 1) asm volatile("cp.async.wait_group 2;");
        else if (c == 2) asm volatile("cp.async.wait_group 1;");
        else             asm volatile("cp.async.wait_group 0;");
        __syncthreads();
#pragma unroll
        for (int kkl = 0; kkl < 4; ++kkl) {
            int kk = 4 * c + kkl;
            u32 a0, a1, a2, a3;
            ldmx4(a0, a1, a2, a3, aA + kk * 16 * 2);
#pragma unroll
            for (int j = 0; j < 4; ++j) {
                u32 b0, b1, b2, b3;
                ldmx4(b0, b1, b2, b3, aB + (j * 16 * WS_S + kk * 16) * 2);
                mmabf(acc[2 * j], a0, a1, a2, a3, b0, b1);
                mmabf(acc[2 * j + 1], a0, a1, a2, a3, b2, b3);
            }
        }
    }

    const int o0 = obase + 16 * wid + gq;
    float bs0 = g_base[b * OUTC + o0], bs1 = g_base[b * OUTC + o0 + 8];
    float sp0 = sp[o0], sp1 = sp[o0 + 8], tp0 = tp[o0], tp1 = tp[o0 + 8];
    float* og0 = out + ((size_t)b * OUTC + o0) * NTOK + nbase;
    float* og1 = og0 + (size_t)8 * NTOK;
#pragma unroll
    for (int t = 0; t < 8; ++t) {
        int n = 8 * t + 2 * qd;
        float2 r0, r1;
        r0.x = fmaxf((bs0 - acc[t].x) * sp0 + tp0, 0.f);
        r0.y = fmaxf((bs0 - acc[t].y) * sp0 + tp0, 0.f);
        r1.x = fmaxf((bs1 - acc[t].z) * sp1 + tp1, 0.f);
        r1.y = fmaxf((bs1 - acc[t].w) * sp1 + tp1, 0.f);
        *(float2*)&og0[n] = r0;
        *(float2*)&og1[n] = r1;
    }
}

extern "C" void kernel_launch(void* const* d_in, const int* in_sizes, int n_in,
                              void* d_out, int out_size) {
    const float* x1 = (const float*)d_in[0];
    const float* x2 = (const float*)d_in[1];
    const float* Wq = (const float*)d_in[2];
    const float* bq = (const float*)d_in[3];
    const float* sq = (const float*)d_in[4];
    const float* tq = (const float*)d_in[5];
    const float* Wk = (const float*)d_in[6];
    const float* bk = (const float*)d_in[7];
    const float* sk = (const float*)d_in[8];
    const float* tk = (const float*)d_in[9];
    const float* Wv = (const float*)d_in[10];
    const float* bv = (const float*)d_in[11];
    const float* sv = (const float*)d_in[12];
    const float* tv = (const float*)d_in[13];
    const float* Wp = (const float*)d_in[14];
    const float* bp = (const float*)d_in[15];
    const float* sp = (const float*)d_in[16];
    const float* tp = (const float*)d_in[17];
    float* out = (float*)d_out;

    cudaFuncSetAttribute(qkv_tc_kernel, cudaFuncAttributeMaxDynamicSharedMemorySize, SMEM_QKV);
    cudaFuncSetAttribute(attn_kernel, cudaFuncAttributeMaxDynamicSharedMemorySize, SMEM_ATTN);
    cudaFuncSetAttribute(projf_tc_kernel, cudaFuncAttributeMaxDynamicSharedMemorySize, SMEM_PF);

    cvt_x_kernel<<<dim3(4096, 2), 256>>>(x1, x2);
    cvt_w_kernel<<<dim3(64, 5), 256>>>(Wq, Wk, Wv, Wp);   // y==4 zeroes csum
    qkv_tc_kernel<<<dim3(NTOK / 64, BATCH, 4), 256, SMEM_QKV>>>(
        bq, sq, tq, bk, sk, tk, bv, sv, tv);
    base_kernel<<<BATCH, 256>>>(Wp, bp);
    attn_kernel<<<dim3(NTOK / 128, BATCH), 256, SMEM_ATTN>>>();
    projf_tc_kernel<<<dim3(NTOK / 64, OUTC / 128, BATCH), 256, SMEM_PF>>>(sp, tp, out);
}